// round 16
// baseline (speedup 1.0000x reference)
#include <cuda_runtime.h>
#include <cuda_bf16.h>
#include <math.h>
#include <stdint.h>

#define NEG_SLOPE 0.1f

// Scratch (__device__ globals: alloc-free rule)
__device__ float    g_kern[16 * 576];   // [b][c*9 + i*3 + j]
__device__ float    g_att [16 * 64];
__device__ uint32_t g_wswz[2048];       // bf16x2 swizzled W image [o][c], 128B rows

__device__ __forceinline__ float lrelu(float x) { return x >= 0.f ? x : NEG_SLOPE * x; }

__device__ __forceinline__ uint32_t bf2(float lo, float hi) {
    uint32_t r;
    asm("cvt.rn.bf16x2.f32 %0, %1, %2;" : "=r"(r) : "f"(hi), "f"(lo));
    return r;
}
__device__ __forceinline__ uint32_t swz(uint32_t byte_off) {   // 128B-row swizzle
    return byte_off ^ ((byte_off >> 3) & 0x70);
}
__device__ __forceinline__ uint32_t smem_u32(const void* p) {
    uint32_t a;
    asm("{ .reg .u64 t; cvta.to.shared.u64 t, %1; cvt.u32.u64 %0, t; }" : "=r"(a) : "l"(p));
    return a;
}

__device__ __forceinline__ void ldm_x4(uint32_t& r0, uint32_t& r1, uint32_t& r2,
                                       uint32_t& r3, uint32_t addr) {
    asm volatile("ldmatrix.sync.aligned.m8n8.x4.shared.b16 {%0,%1,%2,%3}, [%4];"
                 : "=r"(r0), "=r"(r1), "=r"(r2), "=r"(r3) : "r"(addr));
}
__device__ __forceinline__ void ldm_x4_t(uint32_t& r0, uint32_t& r1, uint32_t& r2,
                                         uint32_t& r3, uint32_t addr) {
    asm volatile("ldmatrix.sync.aligned.m8n8.x4.trans.shared.b16 {%0,%1,%2,%3}, [%4];"
                 : "=r"(r0), "=r"(r1), "=r"(r2), "=r"(r3) : "r"(addr));
}
__device__ __forceinline__ void mma_bf16(float* c, uint32_t a0, uint32_t a1,
                                         uint32_t a2, uint32_t a3,
                                         uint32_t b0, uint32_t b1) {
    asm volatile(
        "mma.sync.aligned.m16n8k16.row.col.f32.bf16.bf16.f32 "
        "{%0,%1,%2,%3}, {%4,%5,%6,%7}, {%8,%9}, {%0,%1,%2,%3};"
        : "+f"(c[0]), "+f"(c[1]), "+f"(c[2]), "+f"(c[3])
        : "r"(a0), "r"(a1), "r"(a2), "r"(a3), "r"(b0), "r"(b1));
}

// ============================================================================
// Kernel A: prep with fused dvec mean (coalesced), GEMV chains -> g_kern,
// g_att; block 0 builds the swizzled bf16 W_conv image. 16 blocks x 512 thr.
// ============================================================================
__global__ void __launch_bounds__(512) prep_kernel(
    const float* __restrict__ deg,     // [16,512,8,8]
    const float* __restrict__ W_size,  // [64,512]
    const float* __restrict__ W_k1,    // [8,64]
    const float* __restrict__ W_k2,    // [576,8]
    const float* __restrict__ W_ac,    // [64,512]
    const float* __restrict__ W_du1,   // [8,64]
    const float* __restrict__ W_du2,   // [64,8]
    const float* __restrict__ W_conv)  // [64,64]
{
    const int b    = blockIdx.x;
    const int tid  = threadIdx.x;
    const int lane = tid & 31;
    const int wid  = tid >> 5;   // 0..15

    if (b == 0) {
        #pragma unroll
        for (int k = 0; k < 4; ++k) {
            const int idx = tid + k * 512;        // 0..2047
            const int o  = idx >> 5;
            const int c2 = idx & 31;
            const float lo = W_conv[o * 64 + 2 * c2];
            const float hi = W_conv[o * 64 + 2 * c2 + 1];
            g_wswz[swz((uint32_t)(o * 128 + c2 * 4)) >> 2] = bf2(lo, hi);
        }
    }

    __shared__ float dvecS[512];
    __shared__ float fS[64], faS[64];
    __shared__ float hS[8], hdS[8];

    // dvec: 8 rows per warp-iter; lane = (row_sub<<2) | quarter -> coalesced 2 KB
    {
        const int rsub = lane >> 2;
        const int q    = lane & 3;
        #pragma unroll
        for (int it = 0; it < 4; ++it) {
            const int row = it * 128 + wid * 8 + rsub;
            const float4* p = (const float4*)(deg + ((size_t)b * 512 + row) * 64) + q * 4;
            float s = 0.f;
            #pragma unroll
            for (int j = 0; j < 4; ++j) {
                float4 v = p[j];
                s += (v.x + v.y) + (v.z + v.w);
            }
            s += __shfl_xor_sync(0xffffffffu, s, 1);
            s += __shfl_xor_sync(0xffffffffu, s, 2);
            if (q == 0) dvecS[row] = s * (1.0f / 64.0f);
        }
    }
    __syncthreads();

    // f, fa: warp-per-output-row, coalesced. Warps 0-7 -> fS, warps 8-15 -> faS.
    {
        const float* Wm = (wid < 8) ? W_size : W_ac;
        float* dst      = (wid < 8) ? fS : faS;
        const int obase = (wid & 7) * 8;
        const float4* dv4 = (const float4*)dvecS;
        #pragma unroll
        for (int j = 0; j < 8; ++j) {
            const int c = obase + j;
            const float4* row = (const float4*)(Wm + c * 512);
            float s = 0.f;
            #pragma unroll
            for (int q = 0; q < 4; ++q) {
                float4 v = row[lane + q * 32];
                float4 d = dv4[lane + q * 32];
                s += v.x * d.x + v.y * d.y + v.z * d.z + v.w * d.w;
            }
            #pragma unroll
            for (int off = 16; off > 0; off >>= 1)
                s += __shfl_xor_sync(0xffffffffu, s, off);
            if (lane == 0) dst[c] = s;
        }
    }
    __syncthreads();

    if (tid < 8) {
        float s = 0.f;
        #pragma unroll 16
        for (int c = 0; c < 64; ++c) s = fmaf(fS[c], W_k1[tid * 64 + c], s);
        hS[tid] = lrelu(s);
    } else if (tid >= 32 && tid < 40) {
        const int j = tid - 32;
        float s = 0.f;
        #pragma unroll 16
        for (int c = 0; c < 64; ++c) s = fmaf(faS[c], W_du1[j * 64 + c], s);
        hdS[j] = lrelu(s);
    }
    __syncthreads();

    for (int i = tid; i < 576; i += 512) {
        float s = 0.f;
        #pragma unroll
        for (int j = 0; j < 8; ++j) s = fmaf(hS[j], W_k2[i * 8 + j], s);
        g_kern[b * 576 + i] = s;
    }
    if (tid < 64) {
        float s = 0.f;
        #pragma unroll
        for (int j = 0; j < 8; ++j) s = fmaf(hdS[j], W_du2[tid * 8 + j], s);
        g_att[b * 64 + tid] = 1.0f / (1.0f + expf(-s));
    }
}

// ============================================================================
// Kernel B: depthwise-3x3 + lrelu (fp32) -> bf16 [c][px] (swizzled) ->
// mma.sync bf16 (A = W m=o, B = dw n=px) -> fused wide epilogue.
// Block = (b, 4 output rows): 6 input rows loaded (1.5x vs 2x halo overhead).
// 512 threads, grid 512. 74.8 KB dyn smem, 2 CTA/SM.
// MMA: 16 warps x 2 sequential tasks (row = wid>>3 + 2t, px0 = (wid&7)*16),
// acc registers reused across tasks.
//
// smem map:
//   [0,     65536)  dwC bf16 [4 rows][64 c][128 px], 256B rows, xor (c&7)<<4
//   [65536, 73728)  W   bf16 [64 o][64 c], 128B rows, xor (o&7)<<4
//   [73728, 76032)  kS 576 f32
//   [76032, 76288)  attS 64
//   [76288, 76544)  biasS 64
// ============================================================================
#define C_OFF    0
#define W_OFF    65536
#define K_OFF    73728
#define ATT_OFF  76032
#define BIAS_OFF 76288
#define SMEM_TOTAL 76544

__global__ void __launch_bounds__(512, 2) main_kernel(
    const float* __restrict__ feat,    // [16,64,128,128]
    const float* __restrict__ b_conv,  // [64]
    float* __restrict__ out)
{
    extern __shared__ char smem[];
    const uint32_t smem_base = smem_u32(smem);

    float* kS    = (float*)(smem + K_OFF);
    float* attS  = (float*)(smem + ATT_OFF);
    float* biasS = (float*)(smem + BIAS_OFF);

    const int tid  = threadIdx.x;
    const int bid  = blockIdx.x;
    const int b    = bid >> 5;
    const int h0   = (bid & 31) * 4;
    const int lane = tid & 31;
    const int wid  = tid >> 5;   // 0..15

    // --- stage shared operands ---
    ((uint4*)(smem + W_OFF))[tid] = ((const uint4*)g_wswz)[tid];   // 8 KB
    for (int i = tid; i < 576; i += 512) kS[i] = g_kern[b * 576 + i];
    if (tid < 64) { attS[tid] = g_att[b * 64 + tid]; biasS[tid] = b_conv[tid]; }
    __syncthreads();

    // --- Stage 1: depthwise 3x3 + lrelu over 4 rows (6 input rows) ---
    const float4* feat4 = (const float4*)feat;
    #pragma unroll
    for (int cp = 0; cp < 4; ++cp) {
        const int c = cp * 16 + wid;
        float4 v[6];
        float lf[6], rg[6];
        #pragma unroll
        for (int ri = 0; ri < 6; ++ri) {
            const int r = h0 - 1 + ri;
            if (r >= 0 && r < 128)
                v[ri] = feat4[(((size_t)b * 64 + c) * 128 + r) * 32 + lane];
            else
                v[ri] = make_float4(0.f, 0.f, 0.f, 0.f);
            lf[ri] = __shfl_up_sync(0xffffffffu, v[ri].w, 1);
            rg[ri] = __shfl_down_sync(0xffffffffu, v[ri].x, 1);
            if (lane == 0)  lf[ri] = 0.f;
            if (lane == 31) rg[ri] = 0.f;
        }
        const uint32_t wr_off = (uint32_t)(c * 256) +
            (((uint32_t)(lane * 8)) ^ ((uint32_t)(c & 7) << 4));
        #pragma unroll
        for (int row = 0; row < 4; ++row) {
            float4 a = make_float4(0.f, 0.f, 0.f, 0.f);
            #pragma unroll
            for (int kr = 0; kr < 3; ++kr) {
                const int ri = row + kr;
                const float q0 = kS[c * 9 + kr * 3 + 0];
                const float q1 = kS[c * 9 + kr * 3 + 1];
                const float q2 = kS[c * 9 + kr * 3 + 2];
                a.x = fmaf(q0, lf[ri],   fmaf(q1, v[ri].x, fmaf(q2, v[ri].y, a.x)));
                a.y = fmaf(q0, v[ri].x,  fmaf(q1, v[ri].y, fmaf(q2, v[ri].z, a.y)));
                a.z = fmaf(q0, v[ri].y,  fmaf(q1, v[ri].z, fmaf(q2, v[ri].w, a.z)));
                a.w = fmaf(q0, v[ri].z,  fmaf(q1, v[ri].w, fmaf(q2, rg[ri],  a.w)));
            }
            a.x = lrelu(a.x); a.y = lrelu(a.y); a.z = lrelu(a.z); a.w = lrelu(a.w);
            uint2 pk;
            pk.x = bf2(a.x, a.y);
            pk.y = bf2(a.z, a.w);
            *(uint2*)(smem + C_OFF + row * 16384 + wr_off) = pk;
        }
    }
    __syncthreads();

    // --- MMA + epilogue: 2 sequential tasks per warp ---
    const int px0   = (wid & 7) * 16;
    const int lane7 = lane & 7;

    // A (W) fragment addressing — task-independent
    const uint32_t aRowB = smem_base + W_OFF +
        (uint32_t)((lane7 + ((lane >> 3) & 1) * 8) * 128);
    const uint32_t aColB = (uint32_t)(((lane >> 4) & 1) * 16);
    const uint32_t aXor  = ((uint32_t)lane7) << 4;

    // B (dw) fragment offset within a row slab — task-independent part
    const uint32_t bSlabOff = (uint32_t)((lane7 + (lane & 8)) * 256) +
        ((((uint32_t)((px0 + (((lane >> 4) & 1) << 3)) * 2))) ^ (((uint32_t)lane7) << 4));

    const int g  = lane >> 2;
    const int t2 = (lane & 3) * 2;

    #pragma unroll
    for (int t = 0; t < 2; ++t) {
        const int row = (wid >> 3) + t * 2;           // 0..3
        const uint32_t bBase = smem_base + C_OFF + (uint32_t)(row * 16384) + bSlabOff;

        float acc[4][2][4];   // [mt][n8-tile][c-frag]
        #pragma unroll
        for (int i = 0; i < 4; ++i)
            #pragma unroll
            for (int j = 0; j < 2; ++j)
                #pragma unroll
                for (int k = 0; k < 4; ++k) acc[i][j][k] = 0.f;

        #pragma unroll
        for (int ks = 0; ks < 4; ++ks) {
            uint32_t b0, b1, b2, b3;
            ldm_x4_t(b0, b1, b2, b3, bBase + (uint32_t)(ks * 4096));
            const uint32_t aCol = (aColB + (uint32_t)(ks * 32)) ^ aXor;
            #pragma unroll
            for (int mt = 0; mt < 4; ++mt) {
                uint32_t a0, a1, a2, a3;
                ldm_x4(a0, a1, a2, a3, aRowB + (uint32_t)(mt * 2048) + aCol);
                mma_bf16(acc[mt][0], a0, a1, a2, a3, b0, b1);
                mma_bf16(acc[mt][1], a0, a1, a2, a3, b2, b3);
            }
        }

        // epilogue: + bias + feat*att, float2 loads/stores
        const int h = h0 + row;
        const size_t base = (((size_t)b * 64) * 128 + h) * 128;   // + o*16384 + w

        #pragma unroll
        for (int mt = 0; mt < 4; ++mt) {
            #pragma unroll
            for (int half = 0; half < 2; ++half) {
                const int o = mt * 16 + half * 8 + g;
                const float bb = biasS[o];
                const float aa = attS[o];
                #pragma unroll
                for (int nt = 0; nt < 2; ++nt) {
                    const int w = px0 + nt * 8 + t2;
                    const size_t idx = base + (size_t)o * 16384 + w;
                    float2 f = *(const float2*)&feat[idx];
                    float2 ov;
                    ov.x = acc[mt][nt][half * 2 + 0] + bb + f.x * aa;
                    ov.y = acc[mt][nt][half * 2 + 1] + bb + f.y * aa;
                    *(float2*)&out[idx] = ov;
                }
            }
        }
    }
}

extern "C" void kernel_launch(void* const* d_in, const int* in_sizes, int n_in,
                              void* d_out, int out_size) {
    (void)in_sizes; (void)n_in; (void)out_size;
    const float* feat   = (const float*)d_in[0];
    const float* deg    = (const float*)d_in[1];
    const float* W_size = (const float*)d_in[2];
    const float* W_k1   = (const float*)d_in[3];
    const float* W_k2   = (const float*)d_in[4];
    const float* W_conv = (const float*)d_in[5];
    const float* b_conv = (const float*)d_in[6];
    const float* W_ac   = (const float*)d_in[7];
    const float* W_du1  = (const float*)d_in[8];
    const float* W_du2  = (const float*)d_in[9];
    float* out = (float*)d_out;

    (void)cudaFuncSetAttribute(main_kernel,
                               cudaFuncAttributeMaxDynamicSharedMemorySize, SMEM_TOTAL);

    prep_kernel<<<16, 512>>>(deg, W_size, W_k1, W_k2, W_ac, W_du1, W_du2, W_conv);
    main_kernel<<<16 * 32, 512, SMEM_TOTAL>>>(feat, b_conv, out);
}

// round 17
// speedup vs baseline: 1.4773x; 1.4773x over previous
#include <cuda_runtime.h>
#include <cuda_bf16.h>
#include <math.h>
#include <stdint.h>

#define NEG_SLOPE 0.1f

// Scratch (__device__ globals: alloc-free rule)
__device__ float    g_dvec[16 * 512];
__device__ float    g_kern[16 * 576];   // [b][c*9 + i*3 + j]
__device__ float    g_att [16 * 64];
__device__ uint32_t g_wswz[2048];       // bf16x2 swizzled W image [o][c], 128B rows

__device__ __forceinline__ float lrelu(float x) { return x >= 0.f ? x : NEG_SLOPE * x; }

__device__ __forceinline__ uint32_t bf2(float lo, float hi) {
    uint32_t r;
    asm("cvt.rn.bf16x2.f32 %0, %1, %2;" : "=r"(r) : "f"(hi), "f"(lo));
    return r;
}
__device__ __forceinline__ uint32_t swz(uint32_t byte_off) {   // 128B-row swizzle
    return byte_off ^ ((byte_off >> 3) & 0x70);
}
__device__ __forceinline__ uint32_t smem_u32(const void* p) {
    uint32_t a;
    asm("{ .reg .u64 t; cvta.to.shared.u64 t, %1; cvt.u32.u64 %0, t; }" : "=r"(a) : "l"(p));
    return a;
}

__device__ __forceinline__ void ldm_x4(uint32_t& r0, uint32_t& r1, uint32_t& r2,
                                       uint32_t& r3, uint32_t addr) {
    asm volatile("ldmatrix.sync.aligned.m8n8.x4.shared.b16 {%0,%1,%2,%3}, [%4];"
                 : "=r"(r0), "=r"(r1), "=r"(r2), "=r"(r3) : "r"(addr));
}
__device__ __forceinline__ void ldm_x4_t(uint32_t& r0, uint32_t& r1, uint32_t& r2,
                                         uint32_t& r3, uint32_t addr) {
    asm volatile("ldmatrix.sync.aligned.m8n8.x4.trans.shared.b16 {%0,%1,%2,%3}, [%4];"
                 : "=r"(r0), "=r"(r1), "=r"(r2), "=r"(r3) : "r"(addr));
}
__device__ __forceinline__ void mma_bf16(float* c, uint32_t a0, uint32_t a1,
                                         uint32_t a2, uint32_t a3,
                                         uint32_t b0, uint32_t b1) {
    asm volatile(
        "mma.sync.aligned.m16n8k16.row.col.f32.bf16.bf16.f32 "
        "{%0,%1,%2,%3}, {%4,%5,%6,%7}, {%8,%9}, {%0,%1,%2,%3};"
        : "+f"(c[0]), "+f"(c[1]), "+f"(c[2]), "+f"(c[3])
        : "r"(a0), "r"(a1), "r"(a2), "r"(a3), "r"(b0), "r"(b1));
}

// ============================================================================
// Kernel A1: dvec = mean(deg over 8x8). 1024 blocks x 256 threads (R13/R15
// measured ~4.6-4.9 us).
// ============================================================================
__global__ void __launch_bounds__(256) mean_kernel(const float* __restrict__ deg)
{
    const int lane = threadIdx.x & 31;
    const int gw   = (blockIdx.x * 256 + threadIdx.x) >> 5;   // 0..8191
    const int b = gw >> 9;
    const int d = gw & 511;
    const float* p = deg + ((size_t)b * 512 + d) * 64;
    float s = p[lane] + p[lane + 32];
    #pragma unroll
    for (int off = 16; off > 0; off >>= 1)
        s += __shfl_xor_sync(0xffffffffu, s, off);
    if (lane == 0) g_dvec[b * 512 + d] = s * (1.0f / 64.0f);
}

// ============================================================================
// Kernel A2: GEMV chains -> g_kern, g_att; block 0 builds the swizzled bf16
// W_conv image. 16 blocks x 512 threads. Big GEMV warp-per-row, coalesced.
// ============================================================================
__global__ void __launch_bounds__(512) prep_kernel(
    const float* __restrict__ W_size,  // [64,512]
    const float* __restrict__ W_k1,    // [8,64]
    const float* __restrict__ W_k2,    // [576,8]
    const float* __restrict__ W_ac,    // [64,512]
    const float* __restrict__ W_du1,   // [8,64]
    const float* __restrict__ W_du2,   // [64,8]
    const float* __restrict__ W_conv)  // [64,64]
{
    const int b    = blockIdx.x;
    const int tid  = threadIdx.x;
    const int lane = tid & 31;
    const int wid  = tid >> 5;   // 0..15

    if (b == 0) {
        #pragma unroll
        for (int k = 0; k < 4; ++k) {
            const int idx = tid + k * 512;        // 0..2047
            const int o  = idx >> 5;
            const int c2 = idx & 31;
            const float lo = W_conv[o * 64 + 2 * c2];
            const float hi = W_conv[o * 64 + 2 * c2 + 1];
            g_wswz[swz((uint32_t)(o * 128 + c2 * 4)) >> 2] = bf2(lo, hi);
        }
    }

    __shared__ float dvecS[512];
    __shared__ float fS[64], faS[64];
    __shared__ float hS[8], hdS[8];

    dvecS[tid] = g_dvec[b * 512 + tid];
    __syncthreads();

    // f, fa: warp-per-output-row, coalesced. Warps 0-7 -> fS, warps 8-15 -> faS.
    {
        const float* Wm = (wid < 8) ? W_size : W_ac;
        float* dst      = (wid < 8) ? fS : faS;
        const int obase = (wid & 7) * 8;
        const float4* dv4 = (const float4*)dvecS;
        #pragma unroll
        for (int j = 0; j < 8; ++j) {
            const int c = obase + j;
            const float4* row = (const float4*)(Wm + c * 512);
            float s = 0.f;
            #pragma unroll
            for (int q = 0; q < 4; ++q) {
                float4 v = row[lane + q * 32];
                float4 d = dv4[lane + q * 32];
                s += v.x * d.x + v.y * d.y + v.z * d.z + v.w * d.w;
            }
            #pragma unroll
            for (int off = 16; off > 0; off >>= 1)
                s += __shfl_xor_sync(0xffffffffu, s, off);
            if (lane == 0) dst[c] = s;
        }
    }
    __syncthreads();

    if (tid < 8) {
        float s = 0.f;
        #pragma unroll 16
        for (int c = 0; c < 64; ++c) s = fmaf(fS[c], W_k1[tid * 64 + c], s);
        hS[tid] = lrelu(s);
    } else if (tid >= 32 && tid < 40) {
        const int j = tid - 32;
        float s = 0.f;
        #pragma unroll 16
        for (int c = 0; c < 64; ++c) s = fmaf(faS[c], W_du1[j * 64 + c], s);
        hdS[j] = lrelu(s);
    }
    __syncthreads();

    for (int i = tid; i < 576; i += 512) {
        float s = 0.f;
        #pragma unroll
        for (int j = 0; j < 8; ++j) s = fmaf(hS[j], W_k2[i * 8 + j], s);
        g_kern[b * 576 + i] = s;
    }
    if (tid < 64) {
        float s = 0.f;
        #pragma unroll
        for (int j = 0; j < 8; ++j) s = fmaf(hdS[j], W_du2[tid * 8 + j], s);
        g_att[b * 64 + tid] = 1.0f / (1.0f + expf(-s));
    }
}

// ============================================================================
// Kernel B: depthwise-3x3 + lrelu (fp32) -> bf16 [c][px] (swizzled) ->
// mma.sync bf16 (A = W m=o, B = dw n=px), m32n32 per warp -> fused epilogue.
// Block = (b, 2 rows), 512 threads, grid 1024. 43.8 KB dyn smem, 2 CTA/SM.
// Warp (mg = wid>>3, ng = wid&7): o-group mg*32, row ng>>2, px0 (ng&3)*32.
// Per warp: 16 LDSM.x4 (was 20) + 32 MMA; W-fragment traffic halved.
//
// smem map:
//   [0,     32768)  dwC bf16 [2 rows][64 c][128 px], 256B rows, xor (c&7)<<4
//   [32768, 40960)  W   bf16 [64 o][64 c], 128B rows, xor (o&7)<<4
//   [40960, 43264)  kS 576 f32
//   [43264, 43520)  attS 64
//   [43520, 43776)  biasS 64
// ============================================================================
#define C_OFF    0
#define W_OFF    32768
#define K_OFF    40960
#define ATT_OFF  43264
#define BIAS_OFF 43520
#define SMEM_TOTAL 43776

__global__ void __launch_bounds__(512, 2) main_kernel(
    const float* __restrict__ feat,    // [16,64,128,128]
    const float* __restrict__ b_conv,  // [64]
    float* __restrict__ out)
{
    extern __shared__ char smem[];
    const uint32_t smem_base = smem_u32(smem);

    float* kS    = (float*)(smem + K_OFF);
    float* attS  = (float*)(smem + ATT_OFF);
    float* biasS = (float*)(smem + BIAS_OFF);

    const int tid  = threadIdx.x;
    const int bid  = blockIdx.x;
    const int b    = bid >> 6;
    const int h0   = (bid & 63) * 2;
    const int lane = tid & 31;
    const int wid  = tid >> 5;   // 0..15

    // --- stage shared operands ---
    ((uint4*)(smem + W_OFF))[tid] = ((const uint4*)g_wswz)[tid];   // 8 KB
    for (int i = tid; i < 576; i += 512) kS[i] = g_kern[b * 576 + i];
    if (tid < 64) { attS[tid] = g_att[b * 64 + tid]; biasS[tid] = b_conv[tid]; }
    __syncthreads();

    // --- Stage 1: depthwise 3x3 + lrelu, bf16 into dwC [row][c][px] (swizzled) ---
    const float4* feat4 = (const float4*)feat;
    #pragma unroll
    for (int cp = 0; cp < 4; ++cp) {
        const int c = cp * 16 + wid;
        float4 v[4];
        float lf[4], rg[4];
        #pragma unroll
        for (int ri = 0; ri < 4; ++ri) {
            const int r = h0 - 1 + ri;
            if (r >= 0 && r < 128)
                v[ri] = feat4[(((size_t)b * 64 + c) * 128 + r) * 32 + lane];
            else
                v[ri] = make_float4(0.f, 0.f, 0.f, 0.f);
            lf[ri] = __shfl_up_sync(0xffffffffu, v[ri].w, 1);
            rg[ri] = __shfl_down_sync(0xffffffffu, v[ri].x, 1);
            if (lane == 0)  lf[ri] = 0.f;
            if (lane == 31) rg[ri] = 0.f;
        }
        const uint32_t wr_off = (uint32_t)(c * 256) +
            (((uint32_t)(lane * 8)) ^ ((uint32_t)(c & 7) << 4));
        #pragma unroll
        for (int row = 0; row < 2; ++row) {
            float4 a = make_float4(0.f, 0.f, 0.f, 0.f);
            #pragma unroll
            for (int kr = 0; kr < 3; ++kr) {
                const int ri = row + kr;
                const float q0 = kS[c * 9 + kr * 3 + 0];
                const float q1 = kS[c * 9 + kr * 3 + 1];
                const float q2 = kS[c * 9 + kr * 3 + 2];
                a.x = fmaf(q0, lf[ri],   fmaf(q1, v[ri].x, fmaf(q2, v[ri].y, a.x)));
                a.y = fmaf(q0, v[ri].x,  fmaf(q1, v[ri].y, fmaf(q2, v[ri].z, a.y)));
                a.z = fmaf(q0, v[ri].y,  fmaf(q1, v[ri].z, fmaf(q2, v[ri].w, a.z)));
                a.w = fmaf(q0, v[ri].z,  fmaf(q1, v[ri].w, fmaf(q2, rg[ri],  a.w)));
            }
            a.x = lrelu(a.x); a.y = lrelu(a.y); a.z = lrelu(a.z); a.w = lrelu(a.w);
            uint2 pk;
            pk.x = bf2(a.x, a.y);
            pk.y = bf2(a.z, a.w);
            *(uint2*)(smem + C_OFF + row * 16384 + wr_off) = pk;
        }
    }
    __syncthreads();

    // --- MMA: m32n32 per warp. A = W (m=o, non-trans), B = dw (n=px, trans) ---
    const int mg    = wid >> 3;          // 0..1 -> o32 group
    const int ng    = wid & 7;
    const int row   = ng >> 2;           // 0..1
    const int px0   = (ng & 3) * 32;
    const int lane7 = lane & 7;

    // A fragment (per mt): o_row = mg*32 + mt*16 + lane7 + ((lane>>3)&1)*8
    const uint32_t aRowB = smem_base + W_OFF + (uint32_t)(mg * 32 * 128) +
        (uint32_t)((lane7 + ((lane >> 3) & 1) * 8) * 128);
    const uint32_t aColB = (uint32_t)(((lane >> 4) & 1) * 16);
    const uint32_t aXor  = ((uint32_t)lane7) << 4;

    // B fragment: c = ks*16 + lane7 + (lane&8) ; px = px0 + nt2*16 + ((lane>>4)&1)*8
    const uint32_t bRowB = smem_base + C_OFF + (uint32_t)(row * 16384) +
        (uint32_t)((lane7 + (lane & 8)) * 256);
    const uint32_t bCol0 = (uint32_t)((px0 + (((lane >> 4) & 1) << 3)) * 2);

    float acc[2][4][4];   // [mt][n8-tile (nt2*2+sub)][c-frag]
    #pragma unroll
    for (int i = 0; i < 2; ++i)
        #pragma unroll
        for (int j = 0; j < 4; ++j)
            #pragma unroll
            for (int k = 0; k < 4; ++k) acc[i][j][k] = 0.f;

    #pragma unroll
    for (int ks = 0; ks < 4; ++ks) {
        const uint32_t aCol = (aColB + (uint32_t)(ks * 32)) ^ aXor;
        uint32_t a00, a01, a02, a03, a10, a11, a12, a13;
        ldm_x4(a00, a01, a02, a03, aRowB + aCol);            // mt = 0
        ldm_x4(a10, a11, a12, a13, aRowB + 2048 + aCol);     // mt = 1
        #pragma unroll
        for (int nt2 = 0; nt2 < 2; ++nt2) {
            uint32_t b0, b1, b2, b3;
            ldm_x4_t(b0, b1, b2, b3,
                     bRowB + (uint32_t)(ks * 4096) +
                     ((bCol0 + (uint32_t)(nt2 * 32)) ^ aXor));
            mma_bf16(acc[0][nt2 * 2],     a00, a01, a02, a03, b0, b1);
            mma_bf16(acc[0][nt2 * 2 + 1], a00, a01, a02, a03, b2, b3);
            mma_bf16(acc[1][nt2 * 2],     a10, a11, a12, a13, b0, b1);
            mma_bf16(acc[1][nt2 * 2 + 1], a10, a11, a12, a13, b2, b3);
        }
    }

    // --- epilogue: + bias + feat*att, float2 loads/stores ---
    {
        const int g  = lane >> 2;
        const int t2 = (lane & 3) * 2;
        const int h  = h0 + row;
        const size_t base = (((size_t)b * 64) * 128 + h) * 128;   // + o*16384 + w

        #pragma unroll
        for (int mt = 0; mt < 2; ++mt) {
            #pragma unroll
            for (int half = 0; half < 2; ++half) {
                const int o = mg * 32 + mt * 16 + half * 8 + g;
                const float bb = biasS[o];
                const float aa = attS[o];
                #pragma unroll
                for (int nt2 = 0; nt2 < 2; ++nt2) {
                    #pragma unroll
                    for (int sub = 0; sub < 2; ++sub) {
                        const int w = px0 + nt2 * 16 + sub * 8 + t2;
                        const size_t idx = base + (size_t)o * 16384 + w;
                        float2 f = *(const float2*)&feat[idx];
                        float2 ov;
                        ov.x = acc[mt][nt2 * 2 + sub][half * 2 + 0] + bb + f.x * aa;
                        ov.y = acc[mt][nt2 * 2 + sub][half * 2 + 1] + bb + f.y * aa;
                        *(float2*)&out[idx] = ov;
                    }
                }
            }
        }
    }
}

extern "C" void kernel_launch(void* const* d_in, const int* in_sizes, int n_in,
                              void* d_out, int out_size) {
    (void)in_sizes; (void)n_in; (void)out_size;
    const float* feat   = (const float*)d_in[0];
    const float* deg    = (const float*)d_in[1];
    const float* W_size = (const float*)d_in[2];
    const float* W_k1   = (const float*)d_in[3];
    const float* W_k2   = (const float*)d_in[4];
    const float* W_conv = (const float*)d_in[5];
    const float* b_conv = (const float*)d_in[6];
    const float* W_ac   = (const float*)d_in[7];
    const float* W_du1  = (const float*)d_in[8];
    const float* W_du2  = (const float*)d_in[9];
    float* out = (float*)d_out;

    mean_kernel<<<1024, 256>>>(deg);
    prep_kernel<<<16, 512>>>(W_size, W_k1, W_k2, W_ac, W_du1, W_du2, W_conv);
    main_kernel<<<16 * 64, 512, SMEM_TOTAL>>>(feat, b_conv, out);
}